// round 7
// baseline (speedup 1.0000x reference)
#include <cuda_runtime.h>
#include <cuda_fp16.h>

// CharCNNEncoder: B=128, S=256, W=20, V=256, C_IN=32, C_OUT=64, K=3, pad_idx=0
// Strategy: precompute U[v][k][co] = sum_ci emb_eff[v][ci]*conv_w[co][ci][k]
//   y[word][w][co] = U[c_{w-1}][0][co] + U[c_w][1][co] + U[c_{w+1}][2][co]
//   out[word][co]  = relu(max_w y + b[co])   (bias+relu commute with max)
// U[0] == 0 exactly (pad_idx row zeroed), so conv zero-padding == char index 0.
//
// R4 -> R5: main kernel was shared-crossbar bound (L1=57% SOL, 503MB LDS
// traffic). Table quantized to fp16 -> each LDS.128 carries 8 channels,
// halving both LDS instructions and crossbar bytes. Accumulation in fp32
// (only table quantization error, ~2e-4 rel, vs 1e-3 gate). Bias+ReLU folded
// out of the inner loop (monotonicity), freeing registers and FADDs.

#define NWORDS   32768      // B*S
#define WLEN     20
#define VOCAB    256
#define CIN      32
#define COUT     64
#define KW       3
#define U_HALFS  (VOCAB * KW * COUT)   // 49152 halves = 96 KB
#define U_F4     (U_HALFS / 8)         // 6144 float4 (16B) chunks

#define MAIN_THREADS 1024
#define TPW 8                                 // threads per word
#define WORDS_PER_ITER (MAIN_THREADS / TPW)   // 128
#define GRID_MAIN 148
#define NTILES (NWORDS / WORDS_PER_ITER)      // 256
#define TILES_BASE (NTILES / GRID_MAIN)       // 1
#define TILES_REM  (NTILES - TILES_BASE * GRID_MAIN)  // 108

// fp16 lookup table (96 KB, global backing store).
__device__ __align__(16) unsigned short g_U[U_HALFS];
__device__ int g_chars_stride;

// ---------------------------------------------------------------------------
// Kernel 1: build U in fp16 (+ block 0 probes chars dtype).
// grid = 256 (one block per vocab entry), block = 192: t -> k = t/64, co = t%64
// Probe: int64-LE char data (values 0..255) has every high 32-bit word == 0;
// int32 char data (uniform 0..255) has 192 samples all-zero w.p. ~(1/256)^192.
// ---------------------------------------------------------------------------
__global__ void precompute_U_kernel(const float* __restrict__ emb,
                                    const float* __restrict__ conv_w,
                                    const int* __restrict__ chars32) {
    const int v = blockIdx.x;
    const int t = threadIdx.x;

    if (v == 0) {
        const int hi = chars32[2 * t + 1];
        const int nz = __syncthreads_count(hi != 0);
        if (t == 0) g_chars_stride = (nz == 0) ? 2 : 1;
    }

    __shared__ float e[CIN];
    if (t < CIN) e[t] = emb[v * CIN + t];
    __syncthreads();

    const int k  = t / COUT;   // 0..2
    const int co = t % COUT;   // 0..63

    float s = 0.0f;
#pragma unroll
    for (int ci = 0; ci < CIN; ci++) {
        s = fmaf(e[ci], conv_w[co * (CIN * KW) + ci * KW + k], s);
    }
    if (v == 0) s = 0.0f;   // padding_idx row contributes exactly zero

    g_U[(v * KW + k) * COUT + co] = __half_as_ushort(__float2half_rn(s));
}

// ---------------------------------------------------------------------------
// Kernel 2: main. grid = 148 x 1024 threads, 1 block/SM.
// Block: copy U (96KB) into smem, then sweep 1-2 tiles of 128 words
// (8 threads per word, 8 c_out channels per thread as 4x half2).
// ---------------------------------------------------------------------------
__global__ void __launch_bounds__(MAIN_THREADS, 1)
char_cnn_main_kernel(const int* __restrict__ chars32,
                     const float* __restrict__ conv_b,
                     float4* __restrict__ out) {
    extern __shared__ float smem[];
    float4* sU  = reinterpret_cast<float4*>(smem);             // 6144 float4
    int*    sch = reinterpret_cast<int*>(smem) + U_F4 * 4;     // 128*22 ints

    const int tid = threadIdx.x;
    const int cstride = g_chars_stride;   // 1 = int32 chars, 2 = int64 chars

    // Stage U into shared memory (global table is hot in L2 across blocks).
#pragma unroll 3
    for (int i = tid; i < U_F4; i += MAIN_THREADS) {
        sU[i] = reinterpret_cast<const float4*>(g_U)[i];
    }

    const int g    = tid & (TPW - 1);   // channel group: co = 8g .. 8g+7
    const int slot = tid >> 3;          // word slot within tile (0..127)

    // Bias for this thread's 8 channels (read once; L1/L2 cached, all threads).
    const float4 bA = reinterpret_cast<const float4*>(conv_b)[g * 2];
    const float4 bB = reinterpret_cast<const float4*>(conv_b)[g * 2 + 1];

    // Balanced tile distribution: 256 tiles over 148 blocks (2 or 1 each).
    const int b      = blockIdx.x;
    const int extra  = (b < TILES_REM) ? 1 : 0;
    const int ntiles = TILES_BASE + extra;
    const int tile0  = extra ? (TILES_BASE + 1) * b
                             : TILES_BASE * b + TILES_REM;

    for (int t = 0; t < ntiles; t++) {
        const int base = (tile0 + t) * WORDS_PER_ITER;

        __syncthreads();   // protect sch from previous iteration's readers
                           // (first pass also fences the sU fill before reads)

        // Stage chars for 128 words, padded with char 0 at both ends:
        // sch[slot*22 + 0] = 0, [1..20] = chars, [21] = 0.
        for (int i = tid; i < WORDS_PER_ITER * 22; i += MAIN_THREADS) {
            const int ws = i / 22;
            const int p  = i % 22;
            int c = 0;
            if (p >= 1 && p <= WLEN) {
                const int idx = (base + ws) * WLEN + (p - 1);
                c = chars32[idx * cstride] & 255;
            }
            sch[i] = c;
        }
        __syncthreads();

        const int* sc = sch + slot * 22;

        // Sliding char window: c0 = c_{w-1}, c1 = c_w, c2 = c_{w+1}
        int c1 = sc[0];
        int c2 = sc[1];

        float m0 = -3.0e38f, m1 = m0, m2 = m0, m3 = m0,
              m4 = m0, m5 = m0, m6 = m0, m7 = m0;

#pragma unroll 5
        for (int w = 0; w < WLEN; w++) {
            const int c0 = c1; c1 = c2; c2 = sc[w + 2];

            // sU layout (float4 units): (v*3 + k)*8 + g
            const float4 h0 = sU[c0 * 24 +      g];
            const float4 h1 = sU[c1 * 24 +  8 + g];
            const float4 h2 = sU[c2 * 24 + 16 + g];

            const __half2* p0 = reinterpret_cast<const __half2*>(&h0);
            const __half2* p1 = reinterpret_cast<const __half2*>(&h1);
            const __half2* p2 = reinterpret_cast<const __half2*>(&h2);

            {
                float2 a = __half22float2(p0[0]);
                float2 b2 = __half22float2(p1[0]);
                float2 c = __half22float2(p2[0]);
                m0 = fmaxf(m0, (a.x + b2.x) + c.x);
                m1 = fmaxf(m1, (a.y + b2.y) + c.y);
            }
            {
                float2 a = __half22float2(p0[1]);
                float2 b2 = __half22float2(p1[1]);
                float2 c = __half22float2(p2[1]);
                m2 = fmaxf(m2, (a.x + b2.x) + c.x);
                m3 = fmaxf(m3, (a.y + b2.y) + c.y);
            }
            {
                float2 a = __half22float2(p0[2]);
                float2 b2 = __half22float2(p1[2]);
                float2 c = __half22float2(p2[2]);
                m4 = fmaxf(m4, (a.x + b2.x) + c.x);
                m5 = fmaxf(m5, (a.y + b2.y) + c.y);
            }
            {
                float2 a = __half22float2(p0[3]);
                float2 b2 = __half22float2(p1[3]);
                float2 c = __half22float2(p2[3]);
                m6 = fmaxf(m6, (a.x + b2.x) + c.x);
                m7 = fmaxf(m7, (a.y + b2.y) + c.y);
            }
        }

        // bias + relu (commute with the max-pool above)
        float4 o0, o1;
        o0.x = fmaxf(0.0f, m0 + bA.x);
        o0.y = fmaxf(0.0f, m1 + bA.y);
        o0.z = fmaxf(0.0f, m2 + bA.z);
        o0.w = fmaxf(0.0f, m3 + bA.w);
        o1.x = fmaxf(0.0f, m4 + bB.x);
        o1.y = fmaxf(0.0f, m5 + bB.y);
        o1.z = fmaxf(0.0f, m6 + bB.z);
        o1.w = fmaxf(0.0f, m7 + bB.w);

        out[(base + slot) * 16 + g * 2]     = o0;
        out[(base + slot) * 16 + g * 2 + 1] = o1;
    }
}

// ---------------------------------------------------------------------------
// kernel_launch
// inputs: [0] chars (128,256,20) int32 or int64 (probed)
//         [1] emb f32 (256,32)  [2] conv_w f32 (64,32,3)  [3] conv_b f32 (64)
// output: f32 (128,256,64)
// ---------------------------------------------------------------------------
extern "C" void kernel_launch(void* const* d_in, const int* in_sizes, int n_in,
                              void* d_out, int out_size) {
    const int*   chars32 = (const int*)d_in[0];
    const float* emb     = (const float*)d_in[1];
    const float* conv_w  = (const float*)d_in[2];
    const float* conv_b  = (const float*)d_in[3];
    float4*      out     = (float4*)d_out;

    (void)in_sizes; (void)n_in; (void)out_size;

    const size_t smem_bytes = (size_t)U_HALFS * 2 + (size_t)WORDS_PER_ITER * 22 * 4;
    static bool attr_done = false;  // host-side config, idempotent & deterministic
    if (!attr_done) {
        cudaFuncSetAttribute(char_cnn_main_kernel,
                             cudaFuncAttributeMaxDynamicSharedMemorySize,
                             (int)smem_bytes);
        attr_done = true;
    }

    precompute_U_kernel<<<VOCAB, KW * COUT>>>(emb, conv_w, chars32);
    char_cnn_main_kernel<<<GRID_MAIN, MAIN_THREADS, smem_bytes>>>(
        chars32, conv_b, out);
}